// round 1
// baseline (speedup 1.0000x reference)
#include <cuda_runtime.h>
#include <cstdio>

#define NU 50000
#define NI 100000
#define NN 150000
#define NE 2400000
#define DD 64
#define N_LAYERS 3

// Scratch (static device globals -- no allocation allowed)
__device__ float g_ego[NN * DD];
__device__ float g_side[NN * DD];

// ---------------------------------------------------------------------------
// init: ego = concat(user_emb, item_emb); out[:, 0:64] = ego (raw, no norm)
// ---------------------------------------------------------------------------
__global__ void init_kernel(const float4* __restrict__ ue,
                            const float4* __restrict__ ie,
                            float4* __restrict__ out4) {
    int idx = blockIdx.x * blockDim.x + threadIdx.x;  // over NN*16 float4s
    if (idx >= NN * 16) return;
    int row = idx >> 4;
    int c = idx & 15;
    float4 v = (row < NU) ? ue[row * 16 + c] : ie[(row - NU) * 16 + c];
    ((float4*)g_ego)[idx] = v;
    out4[row * 64 + c] = v;  // out row stride = 256 floats = 64 float4
}

// ---------------------------------------------------------------------------
// spmm scatter: side[dst] += val * ego[src]  (16 threads per edge, v4 red)
// ---------------------------------------------------------------------------
__global__ void spmm_kernel(const int* __restrict__ esrc,
                            const int* __restrict__ edst,
                            const float* __restrict__ ev) {
    int t = blockIdx.x * blockDim.x + threadIdx.x;  // over NE*16
    if (t >= NE * 16) return;
    int e = t >> 4;
    int c = t & 15;
    int s = esrc[e];
    int d = edst[e];
    float v = ev[e];
    float4 x = ((const float4*)g_ego)[s * 16 + c];
    x.x *= v; x.y *= v; x.z *= v; x.w *= v;
    float* p = g_side + d * 64 + c * 4;
    asm volatile("red.global.add.v4.f32 [%0], {%1,%2,%3,%4};"
                 :: "l"(p), "f"(x.x), "f"(x.y), "f"(x.z), "f"(x.w)
                 : "memory");
}

// ---------------------------------------------------------------------------
// dense fused layer:
//   gc = leaky( side @ Wgc^T + bgc )
//   bi = leaky( (ego*side) @ Wbi^T + bbi )
//   ego_new = gc + bi        -> written back to g_ego (in place, own rows only)
//   out[:, 64*(layer+1) : +64] = l2norm(ego_new)
// 128 rows/block, 256 threads, thread tile = 8 rows x 4 cols x 2 matrices.
// ---------------------------------------------------------------------------
__global__ void __launch_bounds__(256, 2) dense_kernel(
    const float* __restrict__ Wgc, const float* __restrict__ bgc,
    const float* __restrict__ Wbi, const float* __restrict__ bbi,
    int layer, float* __restrict__ out) {
    extern __shared__ float sm[];
    float* sX = sm;                  // side tile [128][64]
    float* sE = sm + 128 * 64;       // ego tile  [128][64]
    float* sWg = sm + 2 * 128 * 64;  // Wgc transposed [k][j] = [64][64]
    float* sWb = sWg + 64 * 64;      // Wbi transposed

    const float* Wg = Wgc + layer * 4096;
    const float* Wb = Wbi + layer * 4096;
    int tid = threadIdx.x;
    int row0 = blockIdx.x * 128;

    // Load W transposed: sW[k][j] = W[j][k]
    for (int idx = tid; idx < 1024; idx += 256) {
        int j = idx >> 4;
        int k4 = (idx & 15) << 2;
        float4 wg = *(const float4*)(Wg + j * 64 + k4);
        float4 wb = *(const float4*)(Wb + j * 64 + k4);
        sWg[(k4 + 0) * 64 + j] = wg.x;
        sWg[(k4 + 1) * 64 + j] = wg.y;
        sWg[(k4 + 2) * 64 + j] = wg.z;
        sWg[(k4 + 3) * 64 + j] = wg.w;
        sWb[(k4 + 0) * 64 + j] = wb.x;
        sWb[(k4 + 1) * 64 + j] = wb.y;
        sWb[(k4 + 2) * 64 + j] = wb.z;
        sWb[(k4 + 3) * 64 + j] = wb.w;
    }
    // Load side + ego tiles (zeros for out-of-range rows)
    for (int idx = tid; idx < 2048; idx += 256) {
        int r = idx >> 4;
        int c = idx & 15;
        int row = row0 + r;
        float4 xs = make_float4(0.f, 0.f, 0.f, 0.f);
        float4 xe = xs;
        if (row < NN) {
            xs = ((const float4*)g_side)[row * 16 + c];
            xe = ((const float4*)g_ego)[row * 16 + c];
        }
        *(float4*)(sX + r * 64 + c * 4) = xs;
        *(float4*)(sE + r * 64 + c * 4) = xe;
    }
    __syncthreads();

    int tx = tid & 15;   // column group: cols tx*4 .. tx*4+3
    int ty = tid >> 4;   // row group: rows ty*8 .. ty*8+7

    float ag[8][4], ab[8][4];
#pragma unroll
    for (int i = 0; i < 8; i++)
#pragma unroll
        for (int c = 0; c < 4; c++) { ag[i][c] = 0.f; ab[i][c] = 0.f; }

#pragma unroll 4
    for (int k = 0; k < 64; k++) {
        // uniform k within warp -> broadcast / contiguous smem reads
        float4 wg = *(const float4*)(sWg + k * 64 + tx * 4);
        float4 wb = *(const float4*)(sWb + k * 64 + tx * 4);
#pragma unroll
        for (int i = 0; i < 8; i++) {
            int r = ty * 8 + i;
            float xs = sX[r * 64 + k];
            float xp = sE[r * 64 + k] * xs;
            ag[i][0] += xs * wg.x; ag[i][1] += xs * wg.y;
            ag[i][2] += xs * wg.z; ag[i][3] += xs * wg.w;
            ab[i][0] += xp * wb.x; ab[i][1] += xp * wb.y;
            ab[i][2] += xp * wb.z; ab[i][3] += xp * wb.w;
        }
    }

    float4 bg = *(const float4*)(bgc + layer * 64 + tx * 4);
    float4 bb = *(const float4*)(bbi + layer * 64 + tx * 4);
    const float bgv[4] = {bg.x, bg.y, bg.z, bg.w};
    const float bbv[4] = {bb.x, bb.y, bb.z, bb.w};

    int colbase = (layer + 1) * 64 + tx * 4;
#pragma unroll
    for (int i = 0; i < 8; i++) {
        int row = row0 + ty * 8 + i;
        float v[4];
        float ss = 0.f;
#pragma unroll
        for (int c = 0; c < 4; c++) {
            float s = ag[i][c] + bgv[c];
            s = (s > 0.f) ? s : 0.01f * s;
            float b = ab[i][c] + bbv[c];
            b = (b > 0.f) ? b : 0.01f * b;
            v[c] = s + b;
            ss += v[c] * v[c];
        }
        // reduce sumsq across the 16 threads sharing this row (width-16 xor)
#pragma unroll
        for (int o = 8; o > 0; o >>= 1)
            ss += __shfl_xor_sync(0xffffffffu, ss, o, 16);
        float inv = 1.0f / fmaxf(sqrtf(ss), 1e-12f);
        if (row < NN) {
            float4 raw = make_float4(v[0], v[1], v[2], v[3]);
            ((float4*)g_ego)[row * 16 + tx] = raw;
            float4 nm = make_float4(v[0] * inv, v[1] * inv, v[2] * inv, v[3] * inv);
            *(float4*)(out + (size_t)row * 256 + colbase) = nm;
        }
    }
}

// ---------------------------------------------------------------------------
extern "C" void kernel_launch(void* const* d_in, const int* in_sizes, int n_in,
                              void* d_out, int out_size) {
    const int* esrc = (const int*)d_in[0];
    const int* edst = (const int*)d_in[1];
    const float* ev = (const float*)d_in[2];
    const float* ue = (const float*)d_in[3];
    const float* ie = (const float*)d_in[4];
    const float* Wgc = (const float*)d_in[5];
    const float* bgc = (const float*)d_in[6];
    const float* Wbi = (const float*)d_in[7];
    const float* bbi = (const float*)d_in[8];
    float* out = (float*)d_out;

    void* side_ptr = nullptr;
    cudaGetSymbolAddress(&side_ptr, g_side);
    cudaFuncSetAttribute(dense_kernel, cudaFuncAttributeMaxDynamicSharedMemorySize,
                         98304);

    // layer 0 slice of output + ego init
    init_kernel<<<(NN * 16 + 255) / 256, 256>>>(
        (const float4*)ue, (const float4*)ie, (float4*)out);

    int dense_grid = (NN + 127) / 128;
    for (int l = 0; l < N_LAYERS; l++) {
        cudaMemsetAsync(side_ptr, 0, (size_t)NN * DD * sizeof(float), 0);
        spmm_kernel<<<(NE * 16 + 255) / 256, 256>>>(esrc, edst, ev);
        dense_kernel<<<dense_grid, 256, 98304>>>(Wgc, bgc, Wbi, bbi, l, out);
    }
}